// round 15
// baseline (speedup 1.0000x reference)
#include <cuda_runtime.h>
#include <cuda_bf16.h>
#include <math.h>
#include <stdint.h>

// Inter-layer scratch + sync (allocation-free rule: __device__ globals).
__device__ float g_vL0[729 * 32];
__device__ float g_uR0[729 * 32];
__device__ float g_vL1[27 * 32];
__device__ float g_uR1[27 * 32];
__device__ float g_out0[729];
__device__ float g_out1[27];
__device__ float g_w[32];
__device__ unsigned g_done0[729];
__device__ unsigned g_done1[27];
__device__ unsigned g_grp[27];
__device__ unsigned g_ctr1;
__device__ unsigned g_wflag;

#define PI_HALF 1.57079632679489662f
#define DEPTH 2
#define SF 2048
#define STAGE_BYTES 8192
#define SMEM_DYN (DEPTH * STAGE_BYTES)     // 16 KB -> >=10 CTAs/SM even at 8K granularity... (13 expected)
#define FULL 0xffffffffu

// ---------------- helpers ----------------
__device__ __forceinline__ uint32_t smem_u32(const void* p) {
    return (uint32_t)__cvta_generic_to_shared(p);
}
__device__ __forceinline__ void cpa16(uint32_t d, const float* s) {
    asm volatile("cp.async.cg.shared.global [%0], [%1], 16;" :: "r"(d), "l"(s) : "memory");
}
__device__ __forceinline__ void cp_commit() {
    asm volatile("cp.async.commit_group;" ::: "memory");
}
__device__ __forceinline__ void cp_wait1() {
    asm volatile("cp.async.wait_group 1;" ::: "memory");
}
__device__ __forceinline__ void l2_prefetch_line(const float* p) {
    asm volatile("prefetch.global.L2 [%0];" :: "l"(p));
}
__device__ __forceinline__ float warp_sum(float v) {
#pragma unroll
    for (int o = 16; o > 0; o >>= 1)
        v += __shfl_down_sync(FULL, v, o);
    return v;
}
__device__ __forceinline__ void spin_until(const unsigned* c, unsigned target) {
    unsigned v;
    do {
        asm volatile("ld.global.acquire.gpu.u32 %0, [%1];"
                     : "=r"(v) : "l"(c) : "memory");
        if (v >= target) return;
        __nanosleep(128);
    } while (true);
}
// Warp-wide issue of one 8 KB stage into ring slot.
__device__ __forceinline__ void issue_slot(uint32_t sbase, const float* src_stage,
                                           int slot, int t) {
    const float* src = src_stage + t * 4;
    const uint32_t dst = sbase + slot * STAGE_BYTES + t * 16;
#pragma unroll
    for (int i = 0; i < 16; i++)
        cpa16(dst + i * 512, src + i * 128);
    cp_commit();
}

// Forward ring chain over stages 0..nst-1 (prologue issued inside).
// vbuf holds v on entry/exit. sc1[m]/ss1[m] = cos/sin of site m+1.
__device__ __forceinline__ void ring_fwd(const float* __restrict__ gmid, int nst,
                                         const float* sc1, const float* ss1,
                                         float* vbuf, const float* stg,
                                         uint32_t sbase, int t, bool prologue) {
    if (prologue) {
        issue_slot(sbase, gmid, 0, t);
        issue_slot(sbase, gmid + SF, 1, t);
    }
#pragma unroll 1
    for (int m = 0; m < nst; m++) {
        cp_wait1();
        __syncwarp();
        const float* __restrict__ A = stg + (m & 1) * SF;
        const float c = sc1[m], s = ss1[m];
        float acc = 0.0f;
#pragma unroll
        for (int d = 0; d < 32; d++)
            acc = fmaf(vbuf[d], fmaf(A[d * 64 + t], c, A[d * 64 + 32 + t] * s), acc);
        __syncwarp();
        vbuf[t] = acc;
        if (m + 2 < nst) issue_slot(sbase, gmid + (m + 2) * SF, m & 1, t);
        else             cp_commit();
        __syncwarp();
    }
}

// Backward ring chain over stages hi..lo (descending). u = M u per stage.
// Rotated-LDS row access (conflict-free), proven in R2's final layer.
__device__ __forceinline__ void ring_bwd(const float* __restrict__ gmid,
                                         int hi, int lo,
                                         const float* sc1, const float* ss1,
                                         float* ubuf, const float* stg,
                                         uint32_t sbase, int t, bool prologue) {
    if (prologue) {
        issue_slot(sbase, gmid + hi * SF, 0, t);
        issue_slot(sbase, gmid + (hi - 1) * SF, 1, t);
    }
    const int nst = hi - lo + 1;
#pragma unroll 1
    for (int j = 0; j < nst; j++) {
        const int stage = hi - j;
        cp_wait1();
        __syncwarp();
        const float* __restrict__ A = stg + (j & 1) * SF;
        const float c = sc1[stage], s = ss1[stage];
        float a0 = 0.0f, a1 = 0.0f;
#pragma unroll
        for (int k = 0; k < 32; k++) {
            const int e = (k + t) & 31;
            const float ue = ubuf[e];
            a0 = fmaf(A[t * 64 + e], ue, a0);
            a1 = fmaf(A[t * 64 + 32 + e], ue, a1);
        }
        const float un = fmaf(a0, c, a1 * s);
        __syncwarp();
        ubuf[t] = un;
        if (j + 2 < nst) issue_slot(sbase, gmid + (stage - 2) * SF, j & 1, t);
        else             cp_commit();
        __syncwarp();
    }
}

// Plain-LDG chain / backward step over L2-warm data (final layer only).
__device__ __forceinline__ void chain_lds(const float* __restrict__ mid, int nst,
                                          const float* sc1, const float* ss1,
                                          float* vbuf, int t) {
#pragma unroll 1
    for (int m = 0; m < nst; m++) {
        const float* __restrict__ A = mid + m * SF;
        const float c = sc1[m], s = ss1[m];
        float acc = 0.0f;
#pragma unroll
        for (int d = 0; d < 32; d++)
            acc = fmaf(vbuf[d], fmaf(A[d * 64 + t], c, A[d * 64 + 32 + t] * s), acc);
        __syncwarp();
        vbuf[t] = acc;
        __syncwarp();
    }
}
__device__ __forceinline__ float step_bwd_ldg(const float* __restrict__ g, float u,
                                              int t, float c, float s) {
    const float4* __restrict__ rp = (const float4*)(g + t * 64);
    float4 q[16];
#pragma unroll
    for (int i = 0; i < 16; i++) q[i] = rp[i];
    float acc0 = 0.f, acc1 = 0.f;
#pragma unroll
    for (int i = 0; i < 8; i++) {
        const float4 a = q[i];
        const float4 b = q[8 + i];
        float ue;
        ue = __shfl_sync(FULL, u, 4 * i + 0);
        acc0 = fmaf(a.x, ue, acc0);  acc1 = fmaf(b.x, ue, acc1);
        ue = __shfl_sync(FULL, u, 4 * i + 1);
        acc0 = fmaf(a.y, ue, acc0);  acc1 = fmaf(b.y, ue, acc1);
        ue = __shfl_sync(FULL, u, 4 * i + 2);
        acc0 = fmaf(a.z, ue, acc0);  acc1 = fmaf(b.z, ue, acc1);
        ue = __shfl_sync(FULL, u, 4 * i + 3);
        acc0 = fmaf(a.w, ue, acc0);  acc1 = fmaf(b.w, ue, acc1);
    }
    return fmaf(acc0, c, acc1 * s);
}

// Second-arriver combine. Caller's lanes already stored their own half vector.
// Returns true if this block performed the combine (result in *res on lane 0).
__device__ __forceinline__ bool combine_second(unsigned* done, const float* vL,
                                               const float* uR, float* res, int t) {
    __syncwarp();
    unsigned old = 0;
    if (t == 0) { __threadfence(); old = atomicAdd(done, 1u); }
    old = __shfl_sync(FULL, old, 0);
    if (old == 0) return false;
    __threadfence();
    float p = __ldcg(vL + t) * __ldcg(uR + t);
    p = warp_sum(p);
    if (t == 0) *res = p;
    return true;
}

__global__ void reset_kernel() {
    const int i = threadIdx.x;
    for (int j = i; j < 729; j += 768) g_done0[j] = 0;
    if (i < 27) { g_done1[i] = 0; g_grp[i] = 0; }
    if (i == 27) g_ctr1 = 0;
    if (i == 28) g_wflag = 0;
}

// 1458 blocks x 32 threads.
//   bid <  729 : forward half of layer0 chain n=bid (stages 0..12)
//   bid >= 729 : backward half of layer0 chain n=bid-729 (stages 24..13)
// Whichever half finishes second combines. Tail roles (fixed low IDs):
//   fwd n<27: layer1 fwd half; bwd cn<27: layer1 bwd half (combiner bumps g_ctr1)
//   fwd 27..36: final row o; fwd 37: final backward half.
__global__ void __launch_bounds__(32)
fused_kernel(const float* __restrict__ img,
             const float* __restrict__ l0f, const float* __restrict__ l0m,
             const float* __restrict__ l0l,
             const float* __restrict__ l1f, const float* __restrict__ l1m,
             const float* __restrict__ l1l,
             const float* __restrict__ ff,  const float* __restrict__ fm,
             const float* __restrict__ fl,
             float* __restrict__ out)
{
    extern __shared__ float stg[];                  // DEPTH x 2048 floats
    __shared__ float sc[27], ss[27], vbuf[32];

    const int bid = blockIdx.x;
    const int t = threadIdx.x;
    const bool fwd = (bid < 729);
    const int n = fwd ? bid : bid - 729;
    const uint32_t sbase = smem_u32(stg);
    const float* gm0 = l0m + (long)n * (25 * SF);

    // Ring prologue first: memory in flight before anything else.
    if (fwd) { issue_slot(sbase, gm0, 0, t); issue_slot(sbase, gm0 + SF, 1, t); }
    else     { issue_slot(sbase, gm0 + 24 * SF, 0, t); issue_slot(sbase, gm0 + 23 * SF, 1, t); }

    // Embedding of the 27 squeezed image sites.
    if (t < 27) {
        const int bh = n / 81, bv = (n / 9) % 9, bd = n % 9;
        const int x = t / 9, y = (t / 3) % 3, z = t % 3;
        const float val = img[(3 * bh + x) * 729 + (3 * bv + y) * 27 + (3 * bd + z)];
        float cv, sv;
        sincosf(PI_HALF * val, &sv, &cv);
        sc[t] = cv; ss[t] = sv;
    }
    __syncwarp();

    if (fwd) {
        const float* f0 = l0f + n * 64;
        vbuf[t] = fmaf(f0[t], sc[0], f0[32 + t] * ss[0]);
        __syncwarp();
        ring_fwd(gm0, 13, sc + 1, ss + 1, vbuf, stg, sbase, t, false);
        g_vL0[n * 32 + t] = vbuf[t];
    } else {
        const float* l0 = l0l + n * 64;
        vbuf[t] = fmaf(l0[2 * t], sc[26], l0[2 * t + 1] * ss[26]);
        __syncwarp();
        ring_bwd(gm0, 24, 13, sc + 1, ss + 1, vbuf, stg, sbase, t, false);
        g_uR0[n * 32 + t] = vbuf[t];
    }
    if (combine_second(&g_done0[n], g_vL0 + n * 32, g_uR0 + n * 32, &g_out0[n], t)) {
        if (t == 0) {
            __threadfence();
            const int X = n / 81, Y = (n / 9) % 9, Z = n % 9;
            atomicAdd(&g_grp[(X / 3) * 9 + (Y / 3) * 3 + (Z / 3)], 1u);
        }
    }

    // ---------------- Tails ----------------
    if (fwd && n < 27) {
        // Layer1 forward half, chain n.
        const float* gm1 = l1m + n * (25 * SF);
        issue_slot(sbase, gm1, 0, t); issue_slot(sbase, gm1 + SF, 1, t);
        for (int i = t; i < 11 * 64; i += 32)
            l2_prefetch_line(gm1 + 2 * SF + i * 32);
        spin_until(&g_grp[n], 27u);

        __syncwarp();
        if (t < 27) {
            const int bh = n / 9, bv = (n / 3) % 3, bd = n % 3;
            const int x = t / 9, y = (t / 3) % 3, z = t % 3;
            const float val = __ldcg(&g_out0[(3 * bh + x) * 81 + (3 * bv + y) * 9 + (3 * bd + z)]);
            float cv, sv;
            sincosf(PI_HALF * val, &sv, &cv);
            sc[t] = cv; ss[t] = sv;
        }
        __syncwarp();
        const float* f1 = l1f + n * 64;
        vbuf[t] = fmaf(f1[t], sc[0], f1[32 + t] * ss[0]);
        __syncwarp();
        ring_fwd(gm1, 13, sc + 1, ss + 1, vbuf, stg, sbase, t, false);
        g_vL1[n * 32 + t] = vbuf[t];
        if (combine_second(&g_done1[n], g_vL1 + n * 32, g_uR1 + n * 32, &g_out1[n], t)) {
            if (t == 0) { __threadfence(); atomicAdd(&g_ctr1, 1u); }
        }
        return;
    }
    if (!fwd && n < 27) {
        // Layer1 backward half, chain n.
        const float* gm1 = l1m + n * (25 * SF);
        issue_slot(sbase, gm1 + 24 * SF, 0, t); issue_slot(sbase, gm1 + 23 * SF, 1, t);
        for (int i = t; i < 10 * 64; i += 32)
            l2_prefetch_line(gm1 + 13 * SF + i * 32);
        spin_until(&g_grp[n], 27u);

        __syncwarp();
        if (t < 27) {
            const int bh = n / 9, bv = (n / 3) % 3, bd = n % 3;
            const int x = t / 9, y = (t / 3) % 3, z = t % 3;
            const float val = __ldcg(&g_out0[(3 * bh + x) * 81 + (3 * bv + y) * 9 + (3 * bd + z)]);
            float cv, sv;
            sincosf(PI_HALF * val, &sv, &cv);
            sc[t] = cv; ss[t] = sv;
        }
        __syncwarp();
        const float* l1 = l1l + n * 64;
        vbuf[t] = fmaf(l1[2 * t], sc[26], l1[2 * t + 1] * ss[26]);
        __syncwarp();
        ring_bwd(gm1, 24, 13, sc + 1, ss + 1, vbuf, stg, sbase, t, false);
        g_uR1[n * 32 + t] = vbuf[t];
        if (combine_second(&g_done1[n], g_vL1 + n * 32, g_uR1 + n * 32, &g_out1[n], t)) {
            if (t == 0) { __threadfence(); atomicAdd(&g_ctr1, 1u); }
        }
        return;
    }
    if (fwd && n >= 27 && n < 37) {
        // Final forward row-chain for output o = n-27 (L2-warm LDG).
        const int o = n - 27;
        for (int i = t; i < 13 * 64; i += 32)
            l2_prefetch_line(fm + i * 32);
        spin_until(&g_ctr1, 27u);

        __syncwarp();
        if (t < 27) {
            // (3,3,3) squeeze of g_out1 is the identity permutation
            float cv, sv;
            sincosf(PI_HALF * __ldcg(&g_out1[t]), &sv, &cv);
            sc[t] = cv; ss[t] = sv;
        }
        __syncwarp();
        vbuf[t] = fmaf(ff[o * 32 + t], sc[0], ff[320 + o * 32 + t] * ss[0]);
        __syncwarp();
        chain_lds(fm, 13, sc + 1, ss + 1, vbuf, t);

        spin_until(&g_wflag, 1u);
        const float w = __ldcg(&g_w[t]);
        const float p = warp_sum(vbuf[t] * w);
        if (t == 0) out[o] = p;
        return;
    }
    if (fwd && n == 37) {
        // Final backward half w = M14..M25 * last_emb (L2-warm LDG).
        for (int i = t; i < 12 * 64; i += 32)
            l2_prefetch_line(fm + 13 * SF + i * 32);
        spin_until(&g_ctr1, 27u);

        __syncwarp();
        if (t < 27) {
            float cv, sv;
            sincosf(PI_HALF * __ldcg(&g_out1[t]), &sv, &cv);
            sc[t] = cv; ss[t] = sv;
        }
        __syncwarp();
        float u = fmaf(fl[2 * t], sc[26], fl[2 * t + 1] * ss[26]);
#pragma unroll 1
        for (int m = 24; m >= 13; m--)
            u = step_bwd_ldg(fm + m * SF, u, t, sc[m + 1], ss[m + 1]);
        g_w[t] = u;
        __syncwarp();
        if (t == 0) { __threadfence(); atomicAdd(&g_wflag, 1u); }
    }
}

extern "C" void kernel_launch(void* const* d_in, const int* in_sizes, int n_in,
                              void* d_out, int out_size)
{
    const float* img      = (const float*)d_in[0];
    const float* l0_first = (const float*)d_in[1];
    const float* l0_mid   = (const float*)d_in[2];
    const float* l0_last  = (const float*)d_in[3];
    const float* l1_first = (const float*)d_in[4];
    const float* l1_mid   = (const float*)d_in[5];
    const float* l1_last  = (const float*)d_in[6];
    const float* f_first  = (const float*)d_in[7];
    const float* f_mid    = (const float*)d_in[8];
    const float* f_last   = (const float*)d_in[9];
    float* out = (float*)d_out;

    reset_kernel<<<1, 768>>>();
    fused_kernel<<<1458, 32, SMEM_DYN>>>(img, l0_first, l0_mid, l0_last,
                                         l1_first, l1_mid, l1_last,
                                         f_first, f_mid, f_last, out);
}

// round 16
// speedup vs baseline: 1.0018x; 1.0018x over previous
#include <cuda_runtime.h>
#include <cuda_bf16.h>
#include <math.h>
#include <stdint.h>

// Inter-layer scratch + sync (allocation-free rule: __device__ globals).
__device__ float g_out0[729];
__device__ float g_out1[27];
__device__ float g_vL1[27 * 32];     // layer1 forward half-results
__device__ float g_uR1[27 * 32];     // layer1 backward half-results
__device__ float g_w[32];            // final backward half-result
__device__ unsigned g_grp[27];       // per-layer1-chain producer counters (27 each)
__device__ unsigned g_done1[27];     // layer1 combine rendezvous
__device__ unsigned g_ctr1;          // layer1 completion counter
__device__ unsigned g_wflag;         // final backward-half done flag
__device__ unsigned g_ticket;        // tail-role work-stealing ticket

#define PI_HALF 1.57079632679489662f
#define DEPTH 5
#define SF 2048
#define STAGE_BYTES 8192
#define SMEM_DYN (DEPTH * STAGE_BYTES)   // 40 KB -> 5 CTAs/SM, all 729 resident
#define FULL 0xffffffffu

// ---------------- helpers (R4-verbatim core) ----------------
__device__ __forceinline__ uint32_t smem_u32(const void* p) {
    return (uint32_t)__cvta_generic_to_shared(p);
}
__device__ __forceinline__ void cpa16(uint32_t d, const float* s) {
    asm volatile("cp.async.cg.shared.global [%0], [%1], 16;" :: "r"(d), "l"(s) : "memory");
}
__device__ __forceinline__ void cp_commit() {
    asm volatile("cp.async.commit_group;" ::: "memory");
}
__device__ __forceinline__ void cp_wait4() {
    asm volatile("cp.async.wait_group 4;" ::: "memory");
}
__device__ __forceinline__ void l2_prefetch_line(const float* p) {
    asm volatile("prefetch.global.L2 [%0];" :: "l"(p));
}
__device__ __forceinline__ float warp_sum(float v) {
#pragma unroll
    for (int o = 16; o > 0; o >>= 1)
        v += __shfl_down_sync(FULL, v, o);
    return v;
}
__device__ __forceinline__ void spin_until(const unsigned* c, unsigned target) {
    unsigned v;
    do {
        asm volatile("ld.global.acquire.gpu.u32 %0, [%1];"
                     : "=r"(v) : "l"(c) : "memory");
        if (v >= target) return;
        __nanosleep(128);
    } while (true);
}
// Warp-wide issue of one 8 KB stage into ring slot (stage given, slot given).
__device__ __forceinline__ void issue_slot(uint32_t sbase, const float* src_stage,
                                           int slot, int t) {
    const float* src = src_stage + t * 4;
    const uint32_t dst = sbase + slot * STAGE_BYTES + t * 16;
#pragma unroll
    for (int i = 0; i < 16; i++)
        cpa16(dst + i * 512, src + i * 128);
    cp_commit();
}

// Forward ring chain over stages 0..nst-1. Prologue (min(DEPTH,nst) stages)
// must already be issued. One commit (real or empty) per iteration.
__device__ __forceinline__ void ring_fwd(const float* __restrict__ gmid, int nst,
                                         const float* sc1, const float* ss1,
                                         float* vbuf, const float* stg,
                                         uint32_t sbase, int t)
{
#pragma unroll 1
    for (int m = 0; m < nst; m++) {
        cp_wait4();
        __syncwarp();
        const float* __restrict__ A = stg + (m % DEPTH) * SF;
        const float c = sc1[m], s = ss1[m];
        float acc = 0.0f;
#pragma unroll
        for (int d = 0; d < 32; d++)
            acc = fmaf(vbuf[d], fmaf(A[d * 64 + t], c, A[d * 64 + 32 + t] * s), acc);
        __syncwarp();
        vbuf[t] = acc;
        if (m + DEPTH < nst) issue_slot(sbase, gmid + (m + DEPTH) * SF, m % DEPTH, t);
        else                 cp_commit();
        __syncwarp();
    }
}

// Backward ring chain over stages hi..lo (descending): u <- M u per stage.
// Rotated-LDS row access (conflict-free; proven R2/R3). Prologue issued by caller.
__device__ __forceinline__ void ring_bwd(const float* __restrict__ gmid,
                                         int hi, int lo,
                                         const float* sc1, const float* ss1,
                                         float* ubuf, const float* stg,
                                         uint32_t sbase, int t)
{
    const int nst = hi - lo + 1;
#pragma unroll 1
    for (int j = 0; j < nst; j++) {
        const int stage = hi - j;
        cp_wait4();
        __syncwarp();
        const float* __restrict__ A = stg + (j % DEPTH) * SF;
        const float c = sc1[stage], s = ss1[stage];
        float a0 = 0.0f, a1 = 0.0f;
#pragma unroll
        for (int k = 0; k < 32; k++) {
            const int e = (k + t) & 31;
            const float ue = ubuf[e];
            a0 = fmaf(A[t * 64 + e], ue, a0);
            a1 = fmaf(A[t * 64 + 32 + e], ue, a1);
        }
        const float un = fmaf(a0, c, a1 * s);
        __syncwarp();
        ubuf[t] = un;
        if (j + DEPTH < nst) issue_slot(sbase, gmid + (stage - DEPTH) * SF, j % DEPTH, t);
        else                 cp_commit();
        __syncwarp();
    }
}

// Plain-LDG chain / backward step over L2-warm data (final layer only).
__device__ __forceinline__ void chain_lds(const float* __restrict__ mid, int nst,
                                          const float* sc1, const float* ss1,
                                          float* vbuf, int t)
{
#pragma unroll 1
    for (int m = 0; m < nst; m++) {
        const float* __restrict__ A = mid + m * SF;
        const float c = sc1[m], s = ss1[m];
        float acc = 0.0f;
#pragma unroll
        for (int d = 0; d < 32; d++)
            acc = fmaf(vbuf[d], fmaf(A[d * 64 + t], c, A[d * 64 + 32 + t] * s), acc);
        __syncwarp();
        vbuf[t] = acc;
        __syncwarp();
    }
}
__device__ __forceinline__ float step_bwd_ldg(const float* __restrict__ g, float u,
                                              int t, float c, float s) {
    const float4* __restrict__ rp = (const float4*)(g + t * 64);
    float4 q[16];
#pragma unroll
    for (int i = 0; i < 16; i++) q[i] = rp[i];
    float acc0 = 0.f, acc1 = 0.f;
#pragma unroll
    for (int i = 0; i < 8; i++) {
        const float4 a = q[i];
        const float4 b = q[8 + i];
        float ue;
        ue = __shfl_sync(FULL, u, 4 * i + 0);
        acc0 = fmaf(a.x, ue, acc0);  acc1 = fmaf(b.x, ue, acc1);
        ue = __shfl_sync(FULL, u, 4 * i + 1);
        acc0 = fmaf(a.y, ue, acc0);  acc1 = fmaf(b.y, ue, acc1);
        ue = __shfl_sync(FULL, u, 4 * i + 2);
        acc0 = fmaf(a.z, ue, acc0);  acc1 = fmaf(b.z, ue, acc1);
        ue = __shfl_sync(FULL, u, 4 * i + 3);
        acc0 = fmaf(a.w, ue, acc0);  acc1 = fmaf(b.w, ue, acc1);
    }
    return fmaf(acc0, c, acc1 * s);
}

// Second-arriver combine (proven in R15).
__device__ __forceinline__ bool combine_second(unsigned* done, const float* vL,
                                               const float* uR, float* res, int t) {
    __syncwarp();
    unsigned old = 0;
    if (t == 0) { __threadfence(); old = atomicAdd(done, 1u); }
    old = __shfl_sync(FULL, old, 0);
    if (old == 0) return false;
    __threadfence();
    float p = __ldcg(vL + t) * __ldcg(uR + t);
    p = warp_sum(p);
    if (t == 0) *res = p;
    return true;
}

__global__ void reset_kernel() {
    const int i = threadIdx.x;
    if (i < 27) { g_grp[i] = 0; g_done1[i] = 0; }
    if (i == 27) g_ctr1 = 0;
    if (i == 28) g_wflag = 0;
    if (i == 29) g_ticket = 0;
}

// 729 blocks x 32 threads, one wave (5 CTAs/SM @ 40KB).
// All blocks: layer0 chain n (R4 ring, verbatim). Earliest 65 finishers claim:
//   tk  0..26 : layer1 forward half of chain tk (ring, stages 0..12)
//   tk 27..53 : layer1 backward half of chain tk-27 (ring, stages 24..13)
//   tk 54..63 : final output row o=tk-54 (L2-warm LDG, stages 0..12)
//   tk 64     : final backward half w (L2-warm LDG, stages 24..13)
__global__ void __launch_bounds__(32)
fused_kernel(const float* __restrict__ img,
             const float* __restrict__ l0f, const float* __restrict__ l0m,
             const float* __restrict__ l0l,
             const float* __restrict__ l1f, const float* __restrict__ l1m,
             const float* __restrict__ l1l,
             const float* __restrict__ ff,  const float* __restrict__ fm,
             const float* __restrict__ fl,
             float* __restrict__ out)
{
    extern __shared__ float stg[];                  // DEPTH x 2048 floats
    __shared__ float sc[27], ss[27], vbuf[32];

    const int n = blockIdx.x;
    const int t = threadIdx.x;
    const uint32_t sbase = smem_u32(stg);

    // ---------- Layer 0 (verbatim R4 ring) ----------
    const float* gm0 = l0m + (long)n * (25 * SF);
#pragma unroll
    for (int s = 0; s < DEPTH; s++) issue_slot(sbase, gm0 + s * SF, s, t);

    if (t < 27) {
        const int bh = n / 81, bv = (n / 9) % 9, bd = n % 9;
        const int x = t / 9, y = (t / 3) % 3, z = t % 3;
        const float val = img[(3 * bh + x) * 729 + (3 * bv + y) * 27 + (3 * bd + z)];
        float cv, sv;
        sincosf(PI_HALF * val, &sv, &cv);
        sc[t] = cv; ss[t] = sv;
    }
    __syncwarp();
    {
        const float* f0 = l0f + n * 64;
        vbuf[t] = fmaf(f0[t], sc[0], f0[32 + t] * ss[0]);
    }
    __syncwarp();
    ring_fwd(gm0, 25, sc + 1, ss + 1, vbuf, stg, sbase, t);
    {
        const float* ln = l0l + n * 64;
        const float pv = vbuf[t] * fmaf(ln[2 * t], sc[26], ln[2 * t + 1] * ss[26]);
        const float r = warp_sum(pv);
        if (t == 0) {
            g_out0[n] = r;
            __threadfence();
            const int X = n / 81, Y = (n / 9) % 9, Z = n % 9;
            atomicAdd(&g_grp[(X / 3) * 9 + (Y / 3) * 3 + (Z / 3)], 1u);
        }
    }

    // ---------- Tail role claim (finish-order work stealing) ----------
    unsigned tk = 0;
    if (t == 0) tk = atomicAdd(&g_ticket, 1u);
    tk = __shfl_sync(FULL, tk, 0);
    if (tk >= 65) return;

    if (tk < 27) {
        // ===== Layer1 forward half, chain c (ring stages 0..12) =====
        const int c = tk;
        const float* gm1 = l1m + c * (25 * SF);
#pragma unroll
        for (int s = 0; s < DEPTH; s++) issue_slot(sbase, gm1 + s * SF, s, t);
        for (int i = t; i < 8 * 64; i += 32)           // L2-warm stages 5..12
            l2_prefetch_line(gm1 + DEPTH * SF + i * 32);
        spin_until(&g_grp[c], 27u);

        __syncwarp();
        if (t < 27) {
            const int bh = c / 9, bv = (c / 3) % 3, bd = c % 3;
            const int x = t / 9, y = (t / 3) % 3, z = t % 3;
            const float val = __ldcg(&g_out0[(3 * bh + x) * 81 + (3 * bv + y) * 9 + (3 * bd + z)]);
            float cv, sv;
            sincosf(PI_HALF * val, &sv, &cv);
            sc[t] = cv; ss[t] = sv;
        }
        __syncwarp();
        {
            const float* f1 = l1f + c * 64;
            vbuf[t] = fmaf(f1[t], sc[0], f1[32 + t] * ss[0]);
        }
        __syncwarp();
        ring_fwd(gm1, 13, sc + 1, ss + 1, vbuf, stg, sbase, t);
        g_vL1[c * 32 + t] = vbuf[t];
        if (combine_second(&g_done1[c], g_vL1 + c * 32, g_uR1 + c * 32, &g_out1[c], t)) {
            if (t == 0) { __threadfence(); atomicAdd(&g_ctr1, 1u); }
        }
        return;
    }

    if (tk < 54) {
        // ===== Layer1 backward half, chain c (ring stages 24..13) =====
        const int c = tk - 27;
        const float* gm1 = l1m + c * (25 * SF);
#pragma unroll
        for (int s = 0; s < DEPTH; s++) issue_slot(sbase, gm1 + (24 - s) * SF, s, t);
        for (int i = t; i < 7 * 64; i += 32)           // L2-warm stages 13..19
            l2_prefetch_line(gm1 + 13 * SF + i * 32);
        spin_until(&g_grp[c], 27u);

        __syncwarp();
        if (t < 27) {
            const int bh = c / 9, bv = (c / 3) % 3, bd = c % 3;
            const int x = t / 9, y = (t / 3) % 3, z = t % 3;
            const float val = __ldcg(&g_out0[(3 * bh + x) * 81 + (3 * bv + y) * 9 + (3 * bd + z)]);
            float cv, sv;
            sincosf(PI_HALF * val, &sv, &cv);
            sc[t] = cv; ss[t] = sv;
        }
        __syncwarp();
        {
            const float* l1 = l1l + c * 64;
            vbuf[t] = fmaf(l1[2 * t], sc[26], l1[2 * t + 1] * ss[26]);
        }
        __syncwarp();
        ring_bwd(gm1, 24, 13, sc + 1, ss + 1, vbuf, stg, sbase, t);
        g_uR1[c * 32 + t] = vbuf[t];
        if (combine_second(&g_done1[c], g_vL1 + c * 32, g_uR1 + c * 32, &g_out1[c], t)) {
            if (t == 0) { __threadfence(); atomicAdd(&g_ctr1, 1u); }
        }
        return;
    }

    if (tk < 64) {
        // ===== Final forward row-chain for output o (L2-warm LDG) =====
        const int o = tk - 54;
        for (int i = t; i < 13 * 64; i += 32)          // L2-warm fm stages 0..12
            l2_prefetch_line(fm + i * 32);
        spin_until(&g_ctr1, 27u);

        __syncwarp();
        if (t < 27) {
            // (3,3,3) squeeze of g_out1 is the identity permutation
            float cv, sv;
            sincosf(PI_HALF * __ldcg(&g_out1[t]), &sv, &cv);
            sc[t] = cv; ss[t] = sv;
        }
        __syncwarp();
        vbuf[t] = fmaf(ff[o * 32 + t], sc[0], ff[320 + o * 32 + t] * ss[0]);
        __syncwarp();
        chain_lds(fm, 13, sc + 1, ss + 1, vbuf, t);    // stages 0..12

        spin_until(&g_wflag, 1u);
        const float w = __ldcg(&g_w[t]);
        const float p = warp_sum(vbuf[t] * w);
        if (t == 0) out[o] = p;
        return;
    }

    // ===== tk == 64: final backward half w = M13..M24 * last_emb =====
    for (int i = t; i < 12 * 64; i += 32)              // L2-warm fm stages 13..24
        l2_prefetch_line(fm + 13 * SF + i * 32);
    spin_until(&g_ctr1, 27u);

    __syncwarp();
    if (t < 27) {
        float cv, sv;
        sincosf(PI_HALF * __ldcg(&g_out1[t]), &sv, &cv);
        sc[t] = cv; ss[t] = sv;
    }
    __syncwarp();

    float u = fmaf(fl[2 * t], sc[26], fl[2 * t + 1] * ss[26]);
#pragma unroll 1
    for (int m = 24; m >= 13; m--)
        u = step_bwd_ldg(fm + m * SF, u, t, sc[m + 1], ss[m + 1]);
    g_w[t] = u;
    __syncwarp();
    if (t == 0) { __threadfence(); atomicAdd(&g_wflag, 1u); }
}

extern "C" void kernel_launch(void* const* d_in, const int* in_sizes, int n_in,
                              void* d_out, int out_size)
{
    const float* img      = (const float*)d_in[0];
    const float* l0_first = (const float*)d_in[1];
    const float* l0_mid   = (const float*)d_in[2];
    const float* l0_last  = (const float*)d_in[3];
    const float* l1_first = (const float*)d_in[4];
    const float* l1_mid   = (const float*)d_in[5];
    const float* l1_last  = (const float*)d_in[6];
    const float* f_first  = (const float*)d_in[7];
    const float* f_mid    = (const float*)d_in[8];
    const float* f_last   = (const float*)d_in[9];
    float* out = (float*)d_out;

    reset_kernel<<<1, 32>>>();
    fused_kernel<<<729, 32, SMEM_DYN>>>(img, l0_first, l0_mid, l0_last,
                                        l1_first, l1_mid, l1_last,
                                        f_first, f_mid, f_last, out);
}